// round 1
// baseline (speedup 1.0000x reference)
#include <cuda_runtime.h>
#include <cuda_bf16.h>
#include <math.h>

#define Nn 100000
#define Ee 1600000
#define Gg 64

// ---------------- device scratch (static, no runtime allocation) ----------------
__device__ int   g_cnt[Nn];
__device__ int   g_rowptr[Nn + 1];
__device__ int   g_cursor[Nn];
__device__ int   g_cols[Ee];
__device__ float g_dis[Nn];
__device__ float g_bufA[Nn * 64];
__device__ float g_bufB[Nn * 64];
__device__ float g_stats[128];          // [0..H) sum, [H..2H) sumsq
__device__ int   g_bsum[256];           // scan partials
__device__ float g_pool[Gg * 33];       // per graph: sum[16], max[16], count

// ---------------- small utility kernels ----------------
__global__ void k_zero_cnt() {
    int i = blockIdx.x * 256 + threadIdx.x;
    if (i < Nn) g_cnt[i] = 0;
}
__global__ void k_zero_stats() {
    if (threadIdx.x < 128) g_stats[threadIdx.x] = 0.f;
}
__global__ void k_hist(const int* __restrict__ dst) {
    int e = blockIdx.x * 256 + threadIdx.x;
    if (e < Ee) atomicAdd(&g_cnt[dst[e]], 1);
}

#define SCAN_NB 196   // 196 * 512 = 100352 >= Nn

__global__ void k_scan1() {
    __shared__ int sh[512];
    int t = threadIdx.x, idx = blockIdx.x * 512 + t;
    sh[t] = (idx < Nn) ? g_cnt[idx] : 0;
    __syncthreads();
    for (int off = 256; off > 0; off >>= 1) {
        if (t < off) sh[t] += sh[t + off];
        __syncthreads();
    }
    if (t == 0) g_bsum[blockIdx.x] = sh[0];
}
__global__ void k_scan2() {
    __shared__ int sh[256];
    int t = threadIdx.x;
    int v = (t < SCAN_NB) ? g_bsum[t] : 0;
    sh[t] = v;
    __syncthreads();
    for (int off = 1; off < 256; off <<= 1) {
        int add = (t >= off) ? sh[t - off] : 0;
        __syncthreads();
        sh[t] += add;
        __syncthreads();
    }
    if (t < SCAN_NB) g_bsum[t] = sh[t] - v;   // exclusive
    if (t == 0) g_rowptr[Nn] = Ee;
}
__global__ void k_scan3() {
    __shared__ int sh[512];
    int t = threadIdx.x, idx = blockIdx.x * 512 + t;
    int v = (idx < Nn) ? g_cnt[idx] : 0;
    sh[t] = v;
    __syncthreads();
    for (int off = 1; off < 512; off <<= 1) {
        int add = (t >= off) ? sh[t - off] : 0;
        __syncthreads();
        sh[t] += add;
        __syncthreads();
    }
    if (idx < Nn) {
        int ex = g_bsum[blockIdx.x] + sh[t] - v;
        g_rowptr[idx] = ex;
        g_cursor[idx] = ex;
        g_dis[idx] = rsqrtf((float)(v + 1));   // deg = incoming + self loop
    }
}
__global__ void k_fill(const int* __restrict__ src, const int* __restrict__ dst) {
    int e = blockIdx.x * 256 + threadIdx.x;
    if (e < Ee) {
        int d = dst[e];
        int p = atomicAdd(&g_cursor[d], 1);
        g_cols[p] = src[e];
    }
}

// ---------------- GEMM: out[i,c] = dis[i] * sum_k h[i,k] * W[k,c] ----------------
// block = 256 threads, 128 nodes per block; each thread: 2 nodes x (H/4) channels
template <int K, int H>
__global__ void __launch_bounds__(256) k_gemm(const float* __restrict__ h,
                                              const float* __restrict__ W,
                                              float* __restrict__ out) {
    constexpr int CPT = H / 4;
    __shared__ float Wsm[32 * H];
    __shared__ float xs[128 * 33];
    const int tid = threadIdx.x;
    const int base = blockIdx.x * 128;
    const int ng = tid >> 2;        // 0..63
    const int cl = tid & 3;
    const int r0 = ng * 2, r1 = ng * 2 + 1;

    float acc0[CPT], acc1[CPT];
#pragma unroll
    for (int j = 0; j < CPT; j++) { acc0[j] = 0.f; acc1[j] = 0.f; }

    for (int kc = 0; kc < K; kc += 32) {
        // load W chunk [32][H]
        {
            const float4* Wg = reinterpret_cast<const float4*>(W + kc * H);
            float4* Ws4 = reinterpret_cast<float4*>(Wsm);
#pragma unroll
            for (int i = tid; i < 32 * H / 4; i += 256) Ws4[i] = Wg[i];
        }
        // load x chunk [128][32] into padded smem
#pragma unroll
        for (int j = 0; j < 4; j++) {
            int f = tid + 256 * j;            // float4 index, [0,1024)
            int row = f >> 3, col4 = f & 7;
            float4 v = make_float4(0.f, 0.f, 0.f, 0.f);
            int grow = base + row;
            if (grow < Nn)
                v = *reinterpret_cast<const float4*>(h + (size_t)grow * K + kc + col4 * 4);
            float* d = &xs[row * 33 + col4 * 4];
            d[0] = v.x; d[1] = v.y; d[2] = v.z; d[3] = v.w;
        }
        __syncthreads();
#pragma unroll
        for (int kk = 0; kk < 32; kk++) {
            float x0 = xs[r0 * 33 + kk];
            float x1 = xs[r1 * 33 + kk];
            const float4* wrow = reinterpret_cast<const float4*>(&Wsm[kk * H + cl * CPT]);
#pragma unroll
            for (int j = 0; j < CPT / 4; j++) {
                float4 w = wrow[j];
                acc0[4 * j + 0] += x0 * w.x; acc0[4 * j + 1] += x0 * w.y;
                acc0[4 * j + 2] += x0 * w.z; acc0[4 * j + 3] += x0 * w.w;
                acc1[4 * j + 0] += x1 * w.x; acc1[4 * j + 1] += x1 * w.y;
                acc1[4 * j + 2] += x1 * w.z; acc1[4 * j + 3] += x1 * w.w;
            }
        }
        __syncthreads();
    }
    int grow0 = base + r0, grow1 = base + r1;
    if (grow0 < Nn) {
        float dn = g_dis[grow0];
        float4* o = reinterpret_cast<float4*>(out + (size_t)grow0 * H + cl * CPT);
#pragma unroll
        for (int j = 0; j < CPT / 4; j++)
            o[j] = make_float4(acc0[4 * j] * dn, acc0[4 * j + 1] * dn,
                               acc0[4 * j + 2] * dn, acc0[4 * j + 3] * dn);
    }
    if (grow1 < Nn) {
        float dn = g_dis[grow1];
        float4* o = reinterpret_cast<float4*>(out + (size_t)grow1 * H + cl * CPT);
#pragma unroll
        for (int j = 0; j < CPT / 4; j++)
            o[j] = make_float4(acc1[4 * j] * dn, acc1[4 * j + 1] * dn,
                               acc1[4 * j + 2] * dn, acc1[4 * j + 3] * dn);
    }
}

// ---------------- gather: pre[i] = dis[i]*(hws[i] + sum_{e:dst=i} hws[src]) + b ----------------
// one warp per node, grid-stride; fused BN sum/sumsq accumulation
template <int H>
__global__ void __launch_bounds__(256) k_gather(const float* __restrict__ hws,
                                                const float* __restrict__ b,
                                                float* __restrict__ pre) {
    constexpr int NCH = (H >= 32) ? H / 32 : 1;
    const int lane = threadIdx.x & 31;
    const int warp = (blockIdx.x * blockDim.x + threadIdx.x) >> 5;
    const int nwarps = (gridDim.x * blockDim.x) >> 5;
    const bool act = (H >= 32) || (lane < H);

    int c[NCH];
#pragma unroll
    for (int j = 0; j < NCH; j++) c[j] = lane + 32 * j;

    float s_sum[NCH], s_sq[NCH];
#pragma unroll
    for (int j = 0; j < NCH; j++) { s_sum[j] = 0.f; s_sq[j] = 0.f; }

    for (int node = warp; node < Nn; node += nwarps) {
        int r0 = g_rowptr[node], r1 = g_rowptr[node + 1];
        float acc[NCH];
        if (act) {
#pragma unroll
            for (int j = 0; j < NCH; j++) acc[j] = hws[node * H + c[j]];
        } else {
#pragma unroll
            for (int j = 0; j < NCH; j++) acc[j] = 0.f;
        }
        int p = r0;
        for (; p + 4 <= r1; p += 4) {
            int s0 = g_cols[p], s1 = g_cols[p + 1], s2 = g_cols[p + 2], s3 = g_cols[p + 3];
            if (act) {
#pragma unroll
                for (int j = 0; j < NCH; j++) {
                    float v0 = hws[s0 * H + c[j]];
                    float v1 = hws[s1 * H + c[j]];
                    float v2 = hws[s2 * H + c[j]];
                    float v3 = hws[s3 * H + c[j]];
                    acc[j] += (v0 + v1) + (v2 + v3);
                }
            }
        }
        for (; p < r1; p++) {
            int s = g_cols[p];
            if (act) {
#pragma unroll
                for (int j = 0; j < NCH; j++) acc[j] += hws[s * H + c[j]];
            }
        }
        if (act) {
            float dn = g_dis[node];
#pragma unroll
            for (int j = 0; j < NCH; j++) {
                float v = dn * acc[j] + b[c[j]];
                pre[node * H + c[j]] = v;
                s_sum[j] += v;
                s_sq[j] += v * v;
            }
        }
    }
    if (act) {
#pragma unroll
        for (int j = 0; j < NCH; j++) {
            atomicAdd(&g_stats[c[j]], s_sum[j]);
            atomicAdd(&g_stats[H + c[j]], s_sq[j]);
        }
    }
}

// ---------------- BN normalize + leaky relu (in place) ----------------
template <int H>
__global__ void k_norm(float* __restrict__ hx, const float* __restrict__ gamma,
                       const float* __restrict__ beta) {
    int idx = blockIdx.x * 256 + threadIdx.x;
    if (idx >= Nn * H) return;
    int c = idx & (H - 1);
    float m = g_stats[c] * (1.0f / Nn);
    float var = g_stats[H + c] * (1.0f / Nn) - m * m;
    float rstd = rsqrtf(var + 1e-5f);
    float v = (hx[idx] - m) * rstd * gamma[c] + beta[c];
    hx[idx] = v > 0.f ? v : 0.1f * v;
}

// ---------------- pooling: per-graph sum/max/count over x3 [N,16] ----------------
__device__ __forceinline__ int lower_bound_batch(const int* __restrict__ batch, int g) {
    int lo = 0, hi = Nn;
    while (lo < hi) {
        int m = (lo + hi) >> 1;
        if (batch[m] < g) lo = m + 1; else hi = m;
    }
    return lo;
}

__global__ void k_pool(const float* __restrict__ x3, const int* __restrict__ batch) {
    __shared__ int ss, se;
    __shared__ float ssum[256], smax[256];
    int g = blockIdx.x, t = threadIdx.x;
    if (t == 0) { ss = lower_bound_batch(batch, g); se = lower_bound_batch(batch, g + 1); }
    __syncthreads();
    int s = ss, e = se;
    float sum = 0.f, mx = -3.402823466e+38f;
    int c = t & 15;
    for (int r = s + (t >> 4); r < e; r += 16) {
        float v = x3[r * 16 + c];
        sum += v;
        mx = fmaxf(mx, v);
    }
    ssum[t] = sum; smax[t] = mx;
    __syncthreads();
    for (int off = 128; off >= 16; off >>= 1) {
        if (t < off) { ssum[t] += ssum[t + off]; smax[t] = fmaxf(smax[t], smax[t + off]); }
        __syncthreads();
    }
    if (t < 16) { g_pool[g * 33 + t] = ssum[t]; g_pool[g * 33 + 16 + t] = smax[t]; }
    if (t == 0) g_pool[g * 33 + 32] = (float)(e - s);
}

// ---------------- head: attention pooling + MLP + sigmoid ----------------
__global__ void k_head(const float* __restrict__ attn_w, const float* __restrict__ attn_b,
                       const float* __restrict__ fc1_w, const float* __restrict__ fc1_b,
                       const float* __restrict__ fc2_w, const float* __restrict__ fc2_b,
                       const float* __restrict__ out_w, const float* __restrict__ out_b,
                       float* __restrict__ out) {
    int g = threadIdx.x;
    if (g >= Gg) return;
    float sm[16], mx[16], mean[16];
    float cnt = g_pool[g * 33 + 32];
    float inv = 1.0f / fmaxf(cnt, 1.0f);
#pragma unroll
    for (int k = 0; k < 16; k++) {
        sm[k] = g_pool[g * 33 + k];
        mx[k] = g_pool[g * 33 + 16 + k];
        mean[k] = sm[k] * inv;
    }
    float z[3];
#pragma unroll
    for (int j = 0; j < 3; j++) z[j] = attn_b[j];
#pragma unroll
    for (int k = 0; k < 16; k++) {
#pragma unroll
        for (int j = 0; j < 3; j++) {
            z[j] += mean[k] * attn_w[k * 3 + j]
                  + mx[k]   * attn_w[(16 + k) * 3 + j]
                  + sm[k]   * attn_w[(32 + k) * 3 + j];
        }
    }
    float zm = fmaxf(z[0], fmaxf(z[1], z[2]));
    float e0 = expf(z[0] - zm), e1 = expf(z[1] - zm), e2 = expf(z[2] - zm);
    float is = 1.f / (e0 + e1 + e2);
    float a0 = e0 * is, a1 = e1 * is, a2 = e2 * is;
    float xg[16];
#pragma unroll
    for (int k = 0; k < 16; k++) xg[k] = a0 * mean[k] + a1 * mx[k] + a2 * sm[k];
    float y1[16];
#pragma unroll
    for (int j = 0; j < 16; j++) {
        float acc = fc1_b[j];
#pragma unroll
        for (int k = 0; k < 16; k++) acc += xg[k] * fc1_w[k * 16 + j];
        y1[j] = acc > 0.f ? acc : 0.1f * acc;
    }
    float y2[8];
#pragma unroll
    for (int j = 0; j < 8; j++) {
        float acc = fc2_b[j];
#pragma unroll
        for (int k = 0; k < 16; k++) acc += y1[k] * fc2_w[k * 8 + j];
        y2[j] = acc > 0.f ? acc : 0.1f * acc;
    }
    float o = out_b[0];
#pragma unroll
    for (int k = 0; k < 8; k++) o += y2[k] * out_w[k];
    out[g] = 1.f / (1.f + expf(-o));
}

// ---------------- host launch ----------------
extern "C" void kernel_launch(void* const* d_in, const int* in_sizes, int n_in,
                              void* d_out, int out_size) {
    const float* x      = (const float*)d_in[0];
    const float* W1     = (const float*)d_in[1];
    const float* b1     = (const float*)d_in[2];
    const float* W2     = (const float*)d_in[3];
    const float* b2     = (const float*)d_in[4];
    const float* W3     = (const float*)d_in[5];
    const float* b3     = (const float*)d_in[6];
    const float* g1     = (const float*)d_in[7];
    const float* be1    = (const float*)d_in[8];
    const float* g2     = (const float*)d_in[9];
    const float* be2    = (const float*)d_in[10];
    const float* g3     = (const float*)d_in[11];
    const float* be3    = (const float*)d_in[12];
    const float* attn_w = (const float*)d_in[13];
    const float* attn_b = (const float*)d_in[14];
    const float* fc1_w  = (const float*)d_in[15];
    const float* fc1_b  = (const float*)d_in[16];
    const float* fc2_w  = (const float*)d_in[17];
    const float* fc2_b  = (const float*)d_in[18];
    const float* out_w  = (const float*)d_in[19];
    const float* out_b  = (const float*)d_in[20];
    const int*   ei     = (const int*)d_in[21];
    const int*   batch  = (const int*)d_in[22];

    const int* src = ei;
    const int* dst = ei + Ee;
    float* out = (float*)d_out;

    void *pA = nullptr, *pB = nullptr;
    cudaGetSymbolAddress(&pA, g_bufA);
    cudaGetSymbolAddress(&pB, g_bufB);
    float* bufA = (float*)pA;
    float* bufB = (float*)pB;

    // CSR build + degree norm
    k_zero_cnt<<<(Nn + 255) / 256, 256>>>();
    k_hist<<<(Ee + 255) / 256, 256>>>(dst);
    k_scan1<<<SCAN_NB, 512>>>();
    k_scan2<<<1, 256>>>();
    k_scan3<<<SCAN_NB, 512>>>();
    k_fill<<<(Ee + 255) / 256, 256>>>(src, dst);

    const int gemm_grid = (Nn + 127) / 128;
    const int gather_grid = 1184;   // 148 SMs * 8 blocks

    // Layer 1: 128 -> 64
    k_zero_stats<<<1, 128>>>();
    k_gemm<128, 64><<<gemm_grid, 256>>>(x, W1, bufA);
    k_gather<64><<<gather_grid, 256>>>(bufA, b1, bufB);
    k_norm<64><<<(Nn * 64 + 255) / 256, 256>>>(bufB, g1, be1);

    // Layer 2: 64 -> 32
    k_zero_stats<<<1, 128>>>();
    k_gemm<64, 32><<<gemm_grid, 256>>>(bufB, W2, bufA);
    k_gather<32><<<gather_grid, 256>>>(bufA, b2, bufB);
    k_norm<32><<<(Nn * 32 + 255) / 256, 256>>>(bufB, g2, be2);

    // Layer 3: 32 -> 16
    k_zero_stats<<<1, 128>>>();
    k_gemm<32, 16><<<gemm_grid, 256>>>(bufB, W3, bufA);
    k_gather<16><<<gather_grid, 256>>>(bufA, b3, bufB);
    k_norm<16><<<(Nn * 16 + 255) / 256, 256>>>(bufB, g3, be3);

    // Pool + head
    k_pool<<<Gg, 256>>>(bufB, batch);
    k_head<<<1, 64>>>(attn_w, attn_b, fc1_w, fc1_b, fc2_w, fc2_b, out_w, out_b, out);
}

// round 2
// speedup vs baseline: 1.1823x; 1.1823x over previous
#include <cuda_runtime.h>
#include <cuda_bf16.h>
#include <math.h>

#define Nn 100000
#define Ee 1600000
#define Gg 64

// ---------------- device scratch (static, no runtime allocation) ----------------
__device__ int   g_cnt[Nn];
__device__ int   g_rowptr[Nn + 1];
__device__ int   g_cursor[Nn];
__device__ int   g_cols[Ee];
__device__ float g_dis[Nn];
__device__ float g_bufA[Nn * 64];
__device__ float g_bufB[Nn * 64];
__device__ float g_stats[3 * 128];      // per layer: [0..H) sum, [H..2H) sumsq
__device__ int   g_bsum[256];           // scan partials
__device__ float g_pool[Gg * 33];       // per graph: sum[16], max[16], count

// ---------------- small utility kernels ----------------
__global__ void k_zero() {
    int i = blockIdx.x * 256 + threadIdx.x;
    if (i < Nn) g_cnt[i] = 0;
    if (i < 3 * 128) g_stats[i] = 0.f;
}
__global__ void k_hist(const int* __restrict__ dst) {
    int e = blockIdx.x * 256 + threadIdx.x;
    if (e < Ee) atomicAdd(&g_cnt[dst[e]], 1);
}

#define SCAN_NB 196   // 196 * 512 = 100352 >= Nn

__global__ void k_scan1() {
    __shared__ int sh[512];
    int t = threadIdx.x, idx = blockIdx.x * 512 + t;
    sh[t] = (idx < Nn) ? g_cnt[idx] : 0;
    __syncthreads();
    for (int off = 256; off > 0; off >>= 1) {
        if (t < off) sh[t] += sh[t + off];
        __syncthreads();
    }
    if (t == 0) g_bsum[blockIdx.x] = sh[0];
}
__global__ void k_scan2() {
    __shared__ int sh[256];
    int t = threadIdx.x;
    int v = (t < SCAN_NB) ? g_bsum[t] : 0;
    sh[t] = v;
    __syncthreads();
    for (int off = 1; off < 256; off <<= 1) {
        int add = (t >= off) ? sh[t - off] : 0;
        __syncthreads();
        sh[t] += add;
        __syncthreads();
    }
    if (t < SCAN_NB) g_bsum[t] = sh[t] - v;   // exclusive
    if (t == 0) g_rowptr[Nn] = Ee;
}
__global__ void k_scan3() {
    __shared__ int sh[512];
    int t = threadIdx.x, idx = blockIdx.x * 512 + t;
    int v = (idx < Nn) ? g_cnt[idx] : 0;
    sh[t] = v;
    __syncthreads();
    for (int off = 1; off < 512; off <<= 1) {
        int add = (t >= off) ? sh[t - off] : 0;
        __syncthreads();
        sh[t] += add;
        __syncthreads();
    }
    if (idx < Nn) {
        int ex = g_bsum[blockIdx.x] + sh[t] - v;
        g_rowptr[idx] = ex;
        g_cursor[idx] = ex;
        g_dis[idx] = rsqrtf((float)(v + 1));   // deg = incoming + self loop
    }
}
__global__ void k_fill(const int* __restrict__ src, const int* __restrict__ dst) {
    int e = blockIdx.x * 256 + threadIdx.x;
    if (e < Ee) {
        int d = dst[e];
        int p = atomicAdd(&g_cursor[d], 1);
        g_cols[p] = src[e];
    }
}

// ---------------- GEMM (broadcast scheme) ----------------
// out[i,c] = dis[i] * sum_k f(h[i,k]) * W[k,c]
// where f = identity (NORM=false) or BN-normalize + leaky relu (NORM=true).
// block = 128 threads = 128 nodes; one lane per node; acc[H] in registers;
// W resident in smem, read as warp-uniform LDS.128 (broadcast, conflict-free).
template <int K, int H, bool NORM>
__global__ void __launch_bounds__(128, 4) k_gemm(const float* __restrict__ h,
                                                 const float* __restrict__ W,
                                                 const float* __restrict__ stats,
                                                 const float* __restrict__ gamma,
                                                 const float* __restrict__ beta,
                                                 float* __restrict__ out) {
    __shared__ float Wsm[K * H];
    __shared__ float xs[128 * 17];
    __shared__ float nsc[K], nsh[K];
    const int tid = threadIdx.x;
    const int base = blockIdx.x * 128;
    const int node = base + tid;

    // load full W into smem
    {
        const float4* Wg = reinterpret_cast<const float4*>(W);
        float4* Ws = reinterpret_cast<float4*>(Wsm);
#pragma unroll
        for (int i = tid; i < K * H / 4; i += 128) Ws[i] = Wg[i];
    }
    if (NORM) {
        for (int c = tid; c < K; c += 128) {
            float m = stats[c] * (1.0f / Nn);
            float var = stats[K + c] * (1.0f / Nn) - m * m;
            float rstd = rsqrtf(var + 1e-5f);
            float sc = rstd * gamma[c];
            nsc[c] = sc;
            nsh[c] = beta[c] - m * sc;
        }
    }
    __syncthreads();

    float acc[H];
#pragma unroll
    for (int j = 0; j < H; j++) acc[j] = 0.f;

    for (int kc = 0; kc < K; kc += 16) {
        // stage x chunk [128 nodes][16 cols] into padded smem (with fused BN+lrelu)
#pragma unroll
        for (int jj = 0; jj < 4; jj++) {
            int f = tid + 128 * jj;          // 0..511 float4 slots
            int row = f >> 2, c4 = f & 3;
            int grow = base + row;
            float4 v = make_float4(0.f, 0.f, 0.f, 0.f);
            if (grow < Nn)
                v = *reinterpret_cast<const float4*>(h + (size_t)grow * K + kc + c4 * 4);
            if (NORM) {
                int cb = kc + c4 * 4;
                v.x = v.x * nsc[cb + 0] + nsh[cb + 0]; v.x = v.x > 0.f ? v.x : 0.1f * v.x;
                v.y = v.y * nsc[cb + 1] + nsh[cb + 1]; v.y = v.y > 0.f ? v.y : 0.1f * v.y;
                v.z = v.z * nsc[cb + 2] + nsh[cb + 2]; v.z = v.z > 0.f ? v.z : 0.1f * v.z;
                v.w = v.w * nsc[cb + 3] + nsh[cb + 3]; v.w = v.w > 0.f ? v.w : 0.1f * v.w;
            }
            float* d = &xs[row * 17 + c4 * 4];
            d[0] = v.x; d[1] = v.y; d[2] = v.z; d[3] = v.w;
        }
        __syncthreads();
#pragma unroll
        for (int kk = 0; kk < 16; kk++) {
            float xv = xs[tid * 17 + kk];
            const float4* w4 = reinterpret_cast<const float4*>(&Wsm[(kc + kk) * H]);
#pragma unroll
            for (int j = 0; j < H / 4; j++) {
                float4 w = w4[j];
                acc[4 * j + 0] += xv * w.x;
                acc[4 * j + 1] += xv * w.y;
                acc[4 * j + 2] += xv * w.z;
                acc[4 * j + 3] += xv * w.w;
            }
        }
        __syncthreads();
    }
    if (node < Nn) {
        float dn = g_dis[node];
        float4* o = reinterpret_cast<float4*>(out + (size_t)node * H);
#pragma unroll
        for (int j = 0; j < H / 4; j++)
            o[j] = make_float4(acc[4 * j] * dn, acc[4 * j + 1] * dn,
                               acc[4 * j + 2] * dn, acc[4 * j + 3] * dn);
    }
}

// ---------------- gather: pre[i] = dis[i]*(hws[i] + sum_{e:dst=i} hws[src]) + b ----------------
// one warp per node, grid-stride; fused BN sum/sumsq accumulation
template <int H>
__global__ void __launch_bounds__(256) k_gather(const float* __restrict__ hws,
                                                const float* __restrict__ b,
                                                float* __restrict__ pre,
                                                float* __restrict__ stats) {
    constexpr int NCH = (H >= 32) ? H / 32 : 1;
    const int lane = threadIdx.x & 31;
    const int warp = (blockIdx.x * blockDim.x + threadIdx.x) >> 5;
    const int nwarps = (gridDim.x * blockDim.x) >> 5;
    const bool act = (H >= 32) || (lane < H);

    int c[NCH];
#pragma unroll
    for (int j = 0; j < NCH; j++) c[j] = lane + 32 * j;

    float s_sum[NCH], s_sq[NCH];
#pragma unroll
    for (int j = 0; j < NCH; j++) { s_sum[j] = 0.f; s_sq[j] = 0.f; }

    for (int node = warp; node < Nn; node += nwarps) {
        int r0 = g_rowptr[node], r1 = g_rowptr[node + 1];
        float acc[NCH];
        if (act) {
#pragma unroll
            for (int j = 0; j < NCH; j++) acc[j] = hws[node * H + c[j]];
        } else {
#pragma unroll
            for (int j = 0; j < NCH; j++) acc[j] = 0.f;
        }
        int p = r0;
        for (; p + 4 <= r1; p += 4) {
            int s0 = g_cols[p], s1 = g_cols[p + 1], s2 = g_cols[p + 2], s3 = g_cols[p + 3];
            if (act) {
#pragma unroll
                for (int j = 0; j < NCH; j++) {
                    float v0 = hws[s0 * H + c[j]];
                    float v1 = hws[s1 * H + c[j]];
                    float v2 = hws[s2 * H + c[j]];
                    float v3 = hws[s3 * H + c[j]];
                    acc[j] += (v0 + v1) + (v2 + v3);
                }
            }
        }
        for (; p < r1; p++) {
            int s = g_cols[p];
            if (act) {
#pragma unroll
                for (int j = 0; j < NCH; j++) acc[j] += hws[s * H + c[j]];
            }
        }
        if (act) {
            float dn = g_dis[node];
#pragma unroll
            for (int j = 0; j < NCH; j++) {
                float v = dn * acc[j] + b[c[j]];
                pre[node * H + c[j]] = v;
                s_sum[j] += v;
                s_sq[j] += v * v;
            }
        }
    }
    if (act) {
#pragma unroll
        for (int j = 0; j < NCH; j++) {
            atomicAdd(&stats[c[j]], s_sum[j]);
            atomicAdd(&stats[H + c[j]], s_sq[j]);
        }
    }
}

// ---------------- pooling: per-graph sum/max/count over normalized x3 [N,16] ----------------
__device__ __forceinline__ int lower_bound_batch(const int* __restrict__ batch, int g) {
    int lo = 0, hi = Nn;
    while (lo < hi) {
        int m = (lo + hi) >> 1;
        if (batch[m] < g) lo = m + 1; else hi = m;
    }
    return lo;
}

__global__ void k_pool(const float* __restrict__ x3, const int* __restrict__ batch,
                       const float* __restrict__ stats,
                       const float* __restrict__ gamma, const float* __restrict__ beta) {
    __shared__ int ss, se;
    __shared__ float ssum[256], smax[256];
    int g = blockIdx.x, t = threadIdx.x;
    if (t == 0) { ss = lower_bound_batch(batch, g); se = lower_bound_batch(batch, g + 1); }
    __syncthreads();
    int s = ss, e = se;
    int c = t & 15;
    // per-channel BN scale/shift (layer 3)
    float m = stats[c] * (1.0f / Nn);
    float var = stats[16 + c] * (1.0f / Nn) - m * m;
    float rstd = rsqrtf(var + 1e-5f);
    float sc = rstd * gamma[c];
    float sh = beta[c] - m * sc;

    float sum = 0.f, mx = -3.402823466e+38f;
    for (int r = s + (t >> 4); r < e; r += 16) {
        float v = x3[r * 16 + c] * sc + sh;
        v = v > 0.f ? v : 0.1f * v;
        sum += v;
        mx = fmaxf(mx, v);
    }
    ssum[t] = sum; smax[t] = mx;
    __syncthreads();
    for (int off = 128; off >= 16; off >>= 1) {
        if (t < off) { ssum[t] += ssum[t + off]; smax[t] = fmaxf(smax[t], smax[t + off]); }
        __syncthreads();
    }
    if (t < 16) { g_pool[g * 33 + t] = ssum[t]; g_pool[g * 33 + 16 + t] = smax[t]; }
    if (t == 0) g_pool[g * 33 + 32] = (float)(e - s);
}

// ---------------- head: attention pooling + MLP + sigmoid ----------------
__global__ void k_head(const float* __restrict__ attn_w, const float* __restrict__ attn_b,
                       const float* __restrict__ fc1_w, const float* __restrict__ fc1_b,
                       const float* __restrict__ fc2_w, const float* __restrict__ fc2_b,
                       const float* __restrict__ out_w, const float* __restrict__ out_b,
                       float* __restrict__ out) {
    int g = threadIdx.x;
    if (g >= Gg) return;
    float sm[16], mx[16], mean[16];
    float cnt = g_pool[g * 33 + 32];
    float inv = 1.0f / fmaxf(cnt, 1.0f);
#pragma unroll
    for (int k = 0; k < 16; k++) {
        sm[k] = g_pool[g * 33 + k];
        mx[k] = g_pool[g * 33 + 16 + k];
        mean[k] = sm[k] * inv;
    }
    float z[3];
#pragma unroll
    for (int j = 0; j < 3; j++) z[j] = attn_b[j];
#pragma unroll
    for (int k = 0; k < 16; k++) {
#pragma unroll
        for (int j = 0; j < 3; j++) {
            z[j] += mean[k] * attn_w[k * 3 + j]
                  + mx[k]   * attn_w[(16 + k) * 3 + j]
                  + sm[k]   * attn_w[(32 + k) * 3 + j];
        }
    }
    float zm = fmaxf(z[0], fmaxf(z[1], z[2]));
    float e0 = expf(z[0] - zm), e1 = expf(z[1] - zm), e2 = expf(z[2] - zm);
    float is = 1.f / (e0 + e1 + e2);
    float a0 = e0 * is, a1 = e1 * is, a2 = e2 * is;
    float xg[16];
#pragma unroll
    for (int k = 0; k < 16; k++) xg[k] = a0 * mean[k] + a1 * mx[k] + a2 * sm[k];
    float y1[16];
#pragma unroll
    for (int j = 0; j < 16; j++) {
        float acc = fc1_b[j];
#pragma unroll
        for (int k = 0; k < 16; k++) acc += xg[k] * fc1_w[k * 16 + j];
        y1[j] = acc > 0.f ? acc : 0.1f * acc;
    }
    float y2[8];
#pragma unroll
    for (int j = 0; j < 8; j++) {
        float acc = fc2_b[j];
#pragma unroll
        for (int k = 0; k < 16; k++) acc += y1[k] * fc2_w[k * 8 + j];
        y2[j] = acc > 0.f ? acc : 0.1f * acc;
    }
    float o = out_b[0];
#pragma unroll
    for (int k = 0; k < 8; k++) o += y2[k] * out_w[k];
    out[g] = 1.f / (1.f + expf(-o));
}

// ---------------- host launch ----------------
extern "C" void kernel_launch(void* const* d_in, const int* in_sizes, int n_in,
                              void* d_out, int out_size) {
    const float* x      = (const float*)d_in[0];
    const float* W1     = (const float*)d_in[1];
    const float* b1     = (const float*)d_in[2];
    const float* W2     = (const float*)d_in[3];
    const float* b2     = (const float*)d_in[4];
    const float* W3     = (const float*)d_in[5];
    const float* b3     = (const float*)d_in[6];
    const float* g1     = (const float*)d_in[7];
    const float* be1    = (const float*)d_in[8];
    const float* g2     = (const float*)d_in[9];
    const float* be2    = (const float*)d_in[10];
    const float* g3     = (const float*)d_in[11];
    const float* be3    = (const float*)d_in[12];
    const float* attn_w = (const float*)d_in[13];
    const float* attn_b = (const float*)d_in[14];
    const float* fc1_w  = (const float*)d_in[15];
    const float* fc1_b  = (const float*)d_in[16];
    const float* fc2_w  = (const float*)d_in[17];
    const float* fc2_b  = (const float*)d_in[18];
    const float* out_w  = (const float*)d_in[19];
    const float* out_b  = (const float*)d_in[20];
    const int*   ei     = (const int*)d_in[21];
    const int*   batch  = (const int*)d_in[22];

    const int* src = ei;
    const int* dst = ei + Ee;
    float* out = (float*)d_out;

    void *pA = nullptr, *pB = nullptr, *pS = nullptr;
    cudaGetSymbolAddress(&pA, g_bufA);
    cudaGetSymbolAddress(&pB, g_bufB);
    cudaGetSymbolAddress(&pS, g_stats);
    float* bufA = (float*)pA;
    float* bufB = (float*)pB;
    float* st0 = (float*)pS;          // layer1 stats (sum[64], sq[64])
    float* st1 = st0 + 128;           // layer2 stats (sum[32], sq[32])
    float* st2 = st0 + 256;           // layer3 stats (sum[16], sq[16])

    // CSR build + degree norm (+ zero all BN stats)
    k_zero<<<(Nn + 255) / 256, 256>>>();
    k_hist<<<(Ee + 255) / 256, 256>>>(dst);
    k_scan1<<<SCAN_NB, 512>>>();
    k_scan2<<<1, 256>>>();
    k_scan3<<<SCAN_NB, 512>>>();
    k_fill<<<(Ee + 255) / 256, 256>>>(src, dst);

    const int gemm_grid = (Nn + 127) / 128;   // 782
    const int gather_grid = 1184;             // 148 SMs * 8 blocks

    // Layer 1: 128 -> 64  (raw input, no BN on load)
    k_gemm<128, 64, false><<<gemm_grid, 128>>>(x, W1, nullptr, nullptr, nullptr, bufA);
    k_gather<64><<<gather_grid, 256>>>(bufA, b1, bufB, st0);

    // Layer 2: 64 -> 32  (BN1 + lrelu fused into GEMM load)
    k_gemm<64, 32, true><<<gemm_grid, 128>>>(bufB, W2, st0, g1, be1, bufA);
    k_gather<32><<<gather_grid, 256>>>(bufA, b2, bufB, st1);

    // Layer 3: 32 -> 16  (BN2 + lrelu fused into GEMM load)
    k_gemm<32, 16, true><<<gemm_grid, 128>>>(bufB, W3, st1, g2, be2, bufA);
    k_gather<16><<<gather_grid, 256>>>(bufA, b3, bufB, st2);

    // Pool (BN3 + lrelu fused) + head
    k_pool<<<Gg, 256>>>(bufB, batch, st2, g3, be3);
    k_head<<<1, 64>>>(attn_w, attn_b, fc1_w, fc1_b, fc2_w, fc2_b, out_w, out_b, out);
}